// round 4
// baseline (speedup 1.0000x reference)
#include <cuda_runtime.h>

#define NB 256
#define NC 50000
#define ND 512
#define ND4 (ND / 4)
#define ALPHA_F 0.5f

__device__ int g_labels[NB];

// ---------------------------------------------------------------- K1: labels only (no atomics)
// onehot [NB, NC] f32 as float4; 3.2M float4s; 4 per thread; grid 3125 x 256 exact.
__global__ __launch_bounds__(256) void k_find(const float4* __restrict__ oh) {
    int base = blockIdx.x * 1024 + threadIdx.x;
    float4 v0 = oh[base];
    float4 v1 = oh[base + 256];
    float4 v2 = oh[base + 512];
    float4 v3 = oh[base + 768];
    #pragma unroll
    for (int k = 0; k < 4; k++) {
        float4 w = (k == 0) ? v0 : (k == 1) ? v1 : (k == 2) ? v2 : v3;
        if (w.x != 0.0f || w.y != 0.0f || w.z != 0.0f || w.w != 0.0f) {
            int i = base + k * 256;
            int b = i / (NC / 4);
            int cb = (i - b * (NC / 4)) * 4;
            int off = (w.x != 0.0f) ? 0 : (w.y != 0.0f) ? 1 : (w.z != 0.0f) ? 2 : 3;
            g_labels[b] = cb + off;          // unique writer per sample row
        }
    }
}

// ---------------------------------------------------------------- K2: per-sample distance
__global__ void k_dist(const float* __restrict__ x,
                       const float* __restrict__ centers,
                       float* __restrict__ result) {
    __shared__ float s_warp[4];
    int b = blockIdx.x;
    int t = threadIdx.x;
    int lab = g_labels[b];

    float4 xv = ((const float4*)(x + (size_t)b * ND))[t];
    float4 cv = ((const float4*)(centers + (size_t)lab * ND))[t];

    float dx = xv.x - cv.x, dy = xv.y - cv.y, dz = xv.z - cv.z, dw = xv.w - cv.w;
    float s = dx * dx + dy * dy + dz * dz + dw * dw;
    #pragma unroll
    for (int off = 16; off > 0; off >>= 1)
        s += __shfl_down_sync(0xFFFFFFFFu, s, off);
    if ((t & 31) == 0) s_warp[t >> 5] = s;
    __syncthreads();
    if (t == 0)
        result[b] = s_warp[0] + s_warp[1] + s_warp[2] + s_warp[3];
}

// ---------------------------------------------------------------- K3: fixup touched classes
// Grid = NB blocks x 128 threads. Block b owns class c = labels[b] iff b is the
// FIRST sample with that label. Owner recomputes the full row:
//   out[c] = centers[c] * (1 - inv*cnt) + inv * sum_{label[s]==c} x[s],
//   inv = ALPHA / (cnt + 1)
// overwriting the memcpy'd copy. <=256 active blocks, ~0.5 MB traffic.
__global__ __launch_bounds__(128) void k_fix(const float* __restrict__ x,
                                             const float* __restrict__ centers,
                                             float* __restrict__ out) {
    __shared__ int s_lab[NB];
    int b = blockIdx.x;
    int t = threadIdx.x;
    s_lab[t] = g_labels[t];
    s_lab[t + 128] = g_labels[t + 128];
    __syncthreads();

    int c = s_lab[b];
    // dedup: only the first block with this label proceeds (uniform loop)
    for (int s = 0; s < b; s++)
        if (s_lab[s] == c) return;

    // count + gather sum (coalesced float4 per matching sample)
    int cnt = 0;
    float4 sum = make_float4(0.f, 0.f, 0.f, 0.f);
    for (int s = 0; s < NB; s++) {
        if (s_lab[s] == c) {
            cnt++;
            float4 xv = ((const float4*)(x + (size_t)s * ND))[t];
            sum.x += xv.x; sum.y += xv.y; sum.z += xv.z; sum.w += xv.w;
        }
    }

    float fc = (float)cnt;
    float inv = ALPHA_F / (fc + 1.0f);
    float scale = 1.0f - inv * fc;

    float4 cv = ((const float4*)(centers + (size_t)c * ND))[t];
    float4 o;
    o.x = cv.x * scale + inv * sum.x;
    o.y = cv.y * scale + inv * sum.y;
    o.z = cv.z * scale + inv * sum.z;
    o.w = cv.w * scale + inv * sum.w;
    ((float4*)(out + (size_t)c * ND))[t] = o;
}

// ---------------------------------------------------------------- launch
extern "C" void kernel_launch(void* const* d_in, const int* in_sizes, int n_in,
                              void* d_out, int out_size) {
    const float* x       = (const float*)d_in[0];   // [256, 512]
    const float* onehot  = (const float*)d_in[1];   // [256, 50000]
    const float* centers = (const float*)d_in[2];   // [50000, 512]

    float* result      = (float*)d_out;             // [256]
    float* new_centers = (float*)d_out + NB;        // [50000, 512]

    // Bulk: untouched rows have scale == 1.0 exactly -> pure copy.
    cudaMemcpyAsync(new_centers, centers, (size_t)NC * ND * sizeof(float),
                    cudaMemcpyDeviceToDevice, 0);

    k_find<<<(NB * NC / 4) / 1024, 256>>>((const float4*)onehot);
    k_dist<<<NB, ND4>>>(x, centers, result);
    k_fix<<<NB, 128>>>(x, centers, new_centers);
}

// round 6
// speedup vs baseline: 1.0828x; 1.0828x over previous
#include <cuda_runtime.h>

#define NB 256
#define NC 50000
#define ND 512
#define ND4 (ND / 4)
#define ALPHA_F 0.5f

#define COPY_GROUPS 3125          // groups of 5 blocks: 4 copy + 1 find
#define GRID_MAIN  (COPY_GROUPS * 5)   // 15625

__device__ int g_labels[NB];

// ---------------------------------------------------------------- fused main pass
// copy blocks (4 per group): 512 float4 each -> 12500 * 512 = 6,400,000 = NC*ND/4 exact
// find blocks (1 per group): 1024 float4 each -> 3125 * 1024 = 3,200,000 = NB*NC/4 exact
__global__ __launch_bounds__(256) void k_main(const float4* __restrict__ oh,
                                              const float4* __restrict__ centers,
                                              float4* __restrict__ out) {
    int g = blockIdx.x / 5;
    int r = blockIdx.x - g * 5;
    int t = threadIdx.x;

    if (r < 4) {
        // ---- copy portion: keep centers in L2 (__ldg), stream stores out (__stcs)
        int i = (g * 4 + r) * 512 + t;
        float4 a = __ldg(centers + i);
        float4 b = __ldg(centers + i + 256);
        __stcs(out + i, a);
        __stcs(out + i + 256, b);
    } else {
        // ---- find portion: onehot read-once, evict-first (__ldcs)
        int base = g * 1024 + t;
        float4 v0 = __ldcs(oh + base);
        float4 v1 = __ldcs(oh + base + 256);
        float4 v2 = __ldcs(oh + base + 512);
        float4 v3 = __ldcs(oh + base + 768);
        #pragma unroll
        for (int k = 0; k < 4; k++) {
            float4 w = (k == 0) ? v0 : (k == 1) ? v1 : (k == 2) ? v2 : v3;
            if (w.x != 0.0f || w.y != 0.0f || w.z != 0.0f || w.w != 0.0f) {
                int i = base + k * 256;
                int b = i / (NC / 4);
                int cb = (i - b * (NC / 4)) * 4;
                int off = (w.x != 0.0f) ? 0 : (w.y != 0.0f) ? 1 : (w.z != 0.0f) ? 2 : 3;
                g_labels[b] = cb + off;      // unique writer per sample row
            }
        }
    }
}

// ---------------------------------------------------------------- tail: distance + fixup
// Grid = NB blocks x 128 threads. Block b:
//   1) result[b] = ||x[b] - centers[lab]||^2   (old centers)
//   2) if b is the FIRST sample with label lab: recompute and overwrite the
//      full new_centers row (count + sum over matching samples).
__global__ __launch_bounds__(128) void k_tail(const float* __restrict__ x,
                                              const float* __restrict__ centers,
                                              float* __restrict__ out,
                                              float* __restrict__ result) {
    __shared__ int   s_lab[NB];
    __shared__ float s_warp[4];
    int b = blockIdx.x;
    int t = threadIdx.x;
    s_lab[t]       = g_labels[t];
    s_lab[t + 128] = g_labels[t + 128];
    __syncthreads();

    int lab = s_lab[b];

    float4 xv = ((const float4*)(x + (size_t)b * ND))[t];
    float4 cv = ((const float4*)(centers + (size_t)lab * ND))[t];

    // ---- distance vs OLD center
    float dx = xv.x - cv.x, dy = xv.y - cv.y, dz = xv.z - cv.z, dw = xv.w - cv.w;
    float s = dx * dx + dy * dy + dz * dz + dw * dw;
    #pragma unroll
    for (int off = 16; off > 0; off >>= 1)
        s += __shfl_down_sync(0xFFFFFFFFu, s, off);
    if ((t & 31) == 0) s_warp[t >> 5] = s;
    __syncthreads();
    if (t == 0)
        result[b] = s_warp[0] + s_warp[1] + s_warp[2] + s_warp[3];

    // ---- ownership: first block with this label does the row fixup
    for (int q = 0; q < b; q++)
        if (s_lab[q] == lab) return;

    int cnt = 0;
    float4 sum = make_float4(0.f, 0.f, 0.f, 0.f);
    for (int q = 0; q < NB; q++) {
        if (s_lab[q] == lab) {
            cnt++;
            float4 v = ((const float4*)(x + (size_t)q * ND))[t];
            sum.x += v.x; sum.y += v.y; sum.z += v.z; sum.w += v.w;
        }
    }
    float fc = (float)cnt;
    float inv = ALPHA_F / (fc + 1.0f);
    float scale = 1.0f - inv * fc;

    float4 o;
    o.x = cv.x * scale + inv * sum.x;
    o.y = cv.y * scale + inv * sum.y;
    o.z = cv.z * scale + inv * sum.z;
    o.w = cv.w * scale + inv * sum.w;
    ((float4*)(out + (size_t)lab * ND))[t] = o;
}

// ---------------------------------------------------------------- launch
extern "C" void kernel_launch(void* const* d_in, const int* in_sizes, int n_in,
                              void* d_out, int out_size) {
    const float* x       = (const float*)d_in[0];   // [256, 512]
    const float* onehot  = (const float*)d_in[1];   // [256, 50000]
    const float* centers = (const float*)d_in[2];   // [50000, 512]

    float* result      = (float*)d_out;             // [256]
    float* new_centers = (float*)d_out + NB;        // [50000, 512]

    k_main<<<GRID_MAIN, 256>>>((const float4*)onehot,
                               (const float4*)centers,
                               (float4*)new_centers);
    k_tail<<<NB, 128>>>(x, centers, new_centers, result);
}

// round 9
// speedup vs baseline: 1.3522x; 1.2488x over previous
#include <cuda_runtime.h>

#define NB 256
#define NC 50000
#define ND 512
#define ND4 (ND / 4)
#define ALPHA_F 0.5f

#define COPY_GROUPS 3125               // groups of 5 blocks: 4 copy + 1 find
#define GRID_MAIN  (COPY_GROUPS * 5)   // 15625

__device__ int g_labels[NB];

// ---------------------------------------------------------------- fused main pass (unchanged — at the BW wall)
// copy blocks (4 per group): 512 float4 each -> 12500 * 512 = NC*ND/4 exact
// find blocks (1 per group): 1024 float4 each -> 3125 * 1024 = NB*NC/4 exact
__global__ __launch_bounds__(256) void k_main(const float4* __restrict__ oh,
                                              const float4* __restrict__ centers,
                                              float4* __restrict__ out) {
    int g = blockIdx.x / 5;
    int r = blockIdx.x - g * 5;
    int t = threadIdx.x;

    if (r < 4) {
        int i = (g * 4 + r) * 512 + t;
        float4 a = __ldg(centers + i);
        float4 b = __ldg(centers + i + 256);
        __stcs(out + i, a);
        __stcs(out + i + 256, b);
    } else {
        int base = g * 1024 + t;
        float4 v0 = __ldcs(oh + base);
        float4 v1 = __ldcs(oh + base + 256);
        float4 v2 = __ldcs(oh + base + 512);
        float4 v3 = __ldcs(oh + base + 768);
        #pragma unroll
        for (int k = 0; k < 4; k++) {
            float4 w = (k == 0) ? v0 : (k == 1) ? v1 : (k == 2) ? v2 : v3;
            if (w.x != 0.0f || w.y != 0.0f || w.z != 0.0f || w.w != 0.0f) {
                int i = base + k * 256;
                int b = i / (NC / 4);
                int cb = (i - b * (NC / 4)) * 4;
                int off = (w.x != 0.0f) ? 0 : (w.y != 0.0f) ? 1 : (w.z != 0.0f) ? 2 : 3;
                g_labels[b] = cb + off;      // unique writer per sample row
            }
        }
    }
}

// ---------------------------------------------------------------- tail: distance + fixup, ballot-based
// Grid = NB blocks x 128 threads. Block b:
//   1) result[b] = ||x[b] - centers[lab]||^2  (old centers)
//   2) if b is the FIRST sample with label lab: overwrite new_centers row:
//      out[lab] = centers[lab]*(1-inv*cnt) + inv*sum_{lab[q]==lab} x[q]
// All label logic via 2 ballots -> 8-word bitmask; gather iterates set bits
// only, in deterministic increasing-q order.
__global__ __launch_bounds__(128) void k_tail(const float* __restrict__ x,
                                              const float* __restrict__ centers,
                                              float* __restrict__ out,
                                              float* __restrict__ result) {
    __shared__ int      s_lab[NB];
    __shared__ unsigned s_mask[8];
    __shared__ float    s_warp[4];
    int b = blockIdx.x;
    int t = threadIdx.x;
    int w = t >> 5, lane = t & 31;

    s_lab[t]       = g_labels[t];
    s_lab[t + 128] = g_labels[t + 128];
    __syncthreads();

    int lab = s_lab[b];

    // classify all 256 labels in parallel
    unsigned m0 = __ballot_sync(0xFFFFFFFFu, s_lab[t]       == lab);
    unsigned m1 = __ballot_sync(0xFFFFFFFFu, s_lab[t + 128] == lab);
    if (lane == 0) { s_mask[w] = m0; s_mask[w + 4] = m1; }

    // distance vs OLD center (loads overlap the ballot bookkeeping)
    float4 xv = ((const float4*)(x + (size_t)b * ND))[t];
    float4 cv = ((const float4*)(centers + (size_t)lab * ND))[t];
    float dx = xv.x - cv.x, dy = xv.y - cv.y, dz = xv.z - cv.z, dw = xv.w - cv.w;
    float s = dx * dx + dy * dy + dz * dz + dw * dw;
    #pragma unroll
    for (int off = 16; off > 0; off >>= 1)
        s += __shfl_down_sync(0xFFFFFFFFu, s, off);
    if ((t & 31) == 0) s_warp[t >> 5] = s;
    __syncthreads();                       // covers s_warp AND s_mask
    if (t == 0)
        result[b] = s_warp[0] + s_warp[1] + s_warp[2] + s_warp[3];

    // ownership: first set bit over the 8 words must equal b (uniform)
    int minidx = -1;
    #pragma unroll
    for (int i = 0; i < 8; i++) {
        unsigned m = s_mask[i];
        if (m) { minidx = i * 32 + __ffs(m) - 1; break; }
    }
    if (minidx != b) return;

    int cnt = 0;
    #pragma unroll
    for (int i = 0; i < 8; i++) cnt += __popc(s_mask[i]);

    // gather matching x rows: iterate set bits in increasing order (deterministic)
    float4 sum = make_float4(0.f, 0.f, 0.f, 0.f);
    #pragma unroll
    for (int i = 0; i < 8; i++) {
        unsigned m = s_mask[i];
        while (m) {
            int q = i * 32 + __ffs(m) - 1;
            m &= m - 1;
            float4 v = ((const float4*)(x + (size_t)q * ND))[t];
            sum.x += v.x; sum.y += v.y; sum.z += v.z; sum.w += v.w;
        }
    }

    float fc = (float)cnt;
    float inv = ALPHA_F / (fc + 1.0f);
    float scale = 1.0f - inv * fc;

    float4 o;
    o.x = cv.x * scale + inv * sum.x;
    o.y = cv.y * scale + inv * sum.y;
    o.z = cv.z * scale + inv * sum.z;
    o.w = cv.w * scale + inv * sum.w;
    ((float4*)(out + (size_t)lab * ND))[t] = o;
}

// ---------------------------------------------------------------- launch
extern "C" void kernel_launch(void* const* d_in, const int* in_sizes, int n_in,
                              void* d_out, int out_size) {
    const float* x       = (const float*)d_in[0];   // [256, 512]
    const float* onehot  = (const float*)d_in[1];   // [256, 50000]
    const float* centers = (const float*)d_in[2];   // [50000, 512]

    float* result      = (float*)d_out;             // [256]
    float* new_centers = (float*)d_out + NB;        // [50000, 512]

    k_main<<<GRID_MAIN, 256>>>((const float4*)onehot,
                               (const float4*)centers,
                               (float4*)new_centers);
    k_tail<<<NB, 128>>>(x, centers, new_centers, result);
}